// round 9
// baseline (speedup 1.0000x reference)
#include <cuda_runtime.h>
#include <cstdint>
#include <math.h>

#define Bb 64
#define Tt 512
#define Ff 256
#define Hh 512
#define TFs (Tt*Ff)
#define GRIDN 128
#define NTHR 768
#define WSTRIDE 772                 // floats per weight row (768 + 4 pad)
#define VROWB 144                   // bytes per b-row in a 32-k slot (36 floats)
#define VSLOTB 9216                 // 64 rows * 144 B
#define WS_BYTES (24*WSTRIDE*4)     // 74112
#define SMEM_BYTES (WS_BYTES + 12*VSLOTB)  // 74112 + 110592 = 184704
#define OST (Tt*2*Hh)

typedef unsigned long long ull;

// static device scratch (no allocations allowed)
__device__ float g_h[2][2][Bb][Hh];   // [dir][slot][b][hcol]
__device__ ull   g_barc[32];          // per-direction monotonic counters

// ---------------- helpers ----------------
static __device__ __forceinline__ ull fma2(ull a, ull b, ull c) {
    ull d; asm("fma.rn.f32x2 %0, %1, %2, %3;" : "=l"(d) : "l"(a), "l"(b), "l"(c));
    return d;
}
static __device__ __forceinline__ void add2(ull &a, ull b) {
    asm("add.rn.f32x2 %0, %0, %1;" : "+l"(a) : "l"(b));
}
static __device__ __forceinline__ float lof(ull x) { return __uint_as_float((unsigned)x); }
static __device__ __forceinline__ float hif(ull x) { return __uint_as_float((unsigned)(x >> 32)); }

// VOLATILE shared load (load-bearing: prevents hoisting across barrier asms —
// the R5/R6 correctness bug).
#define LDS128O(base, O, a, b) \
    asm volatile("ld.shared.v2.b64 {%0,%1}, [%2+" #O "];" : "=l"(a), "=l"(b) : "r"(base))

static __device__ __forceinline__ void cpa16(unsigned s, const float4* g) {
    asm volatile("cp.async.cg.shared.global [%0], [%1], 16;"
                 :: "r"(s), "l"(__cvta_generic_to_global((const void*)g)));
}
static __device__ __forceinline__ void cpa_commit() {
    asm volatile("cp.async.commit_group;");
}
template<int N> static __device__ __forceinline__ void cpa_wait() {
    asm volatile("cp.async.wait_group %0;" :: "n"(N) : "memory");
}

static __device__ __forceinline__ float sigf(float x) {
    return __fdividef(1.f, 1.f + __expf(-x));
}
static __device__ __forceinline__ float tanf_fast(float x) {
    return __fdividef(2.f, 1.f + __expf(-2.f * x)) - 1.f;
}

// partition-scoped barrier (128 threads), ids 1..6
static __device__ __forceinline__ void barp(int p) {
    asm volatile("bar.sync %0, 128;" :: "r"(p + 1) : "memory");
}

// per-direction grid barrier: 64 arrivals, monotonic (graph-replay safe)
static __device__ __forceinline__ void grid_barrier(int d) {
    __threadfence();
    __syncthreads();
    if (threadIdx.x == 0) {
        ull* ctr = &g_barc[d * 16];
        ull old;
        asm volatile("atom.release.gpu.global.add.u64 %0, [%1], 1;"
                     : "=l"(old) : "l"(ctr) : "memory");
        ull target = (old / 64ULL + 1ULL) * 64ULL;
        ull cur = old + 1ULL;
        while (cur < target) {
            asm volatile("ld.acquire.gpu.global.u64 %0, [%1];"
                         : "=l"(cur) : "l"(ctr) : "memory");
            if (cur < target) __nanosleep(20);
        }
        __threadfence();
    }
    __syncthreads();
}

// stage one 32k x 64b chunk (8 KB) into a slot; 4 cp.async per thread
static __device__ __forceinline__ void stage32(unsigned dst, const float* sb,
                                               int sstr, int tid2) {
#pragma unroll
    for (int j = 0; j < 4; ++j) {
        int idx = tid2 + j * 128;
        int b = idx >> 3, f = idx & 7;
        cpa16(dst + (unsigned)(b * VROWB + f * 16),
              (const float4*)(sb + (size_t)b * sstr) + f);
    }
    cpa_commit();
}

// one 4-k micro-iter: 7 LDS.128 + 24 fma.f32x2 (4 b x 3 gates)
#define GITER(O) { ull x0,x1,y0,y1,u0,u1,v0,v1,q0,q1,s0,s1,w0,w1; \
  LDS128O(va0,O,x0,x1); LDS128O(va1,O,y0,y1); \
  LDS128O(va2,O,u0,u1); LDS128O(va3,O,v0,v1); \
  LDS128O(wra,O,q0,q1); LDS128O(wza,O,s0,s1); LDS128O(wna,O,w0,w1); \
  aR0=fma2(x0,q0,aR0); aR0=fma2(x1,q1,aR0); \
  aR1=fma2(y0,q0,aR1); aR1=fma2(y1,q1,aR1); \
  aR2=fma2(u0,q0,aR2); aR2=fma2(u1,q1,aR2); \
  aR3=fma2(v0,q0,aR3); aR3=fma2(v1,q1,aR3); \
  aZ0=fma2(x0,s0,aZ0); aZ0=fma2(x1,s1,aZ0); \
  aZ1=fma2(y0,s0,aZ1); aZ1=fma2(y1,s1,aZ1); \
  aZ2=fma2(u0,s0,aZ2); aZ2=fma2(u1,s1,aZ2); \
  aZ3=fma2(v0,s0,aZ3); aZ3=fma2(v1,s1,aZ3); \
  aN0=fma2(x0,w0,aN0); aN0=fma2(x1,w1,aN0); \
  aN1=fma2(y0,w0,aN1); aN1=fma2(y1,w1,aN1); \
  aN2=fma2(u0,w0,aN2); aN2=fma2(u1,w1,aN2); \
  aN3=fma2(v0,w0,aN3); aN3=fma2(v1,w1,aN3); }

// one 32-k chunk: 8 GITERs
#define COMPUTE_CHUNK(SLOTBASE, KK) { \
  const unsigned va0 = (SLOTBASE) + vb0, va1 = (SLOTBASE) + vb1, \
                 va2 = (SLOTBASE) + vb2, va3 = (SLOTBASE) + vb3; \
  const unsigned wra = wrB + (unsigned)(KK) * 4u, \
                 wza = wzB + (unsigned)(KK) * 4u, \
                 wna = wnB + (unsigned)(KK) * 4u; \
  GITER(0)  GITER(16) GITER(32) GITER(48) \
  GITER(64) GITER(80) GITER(96) GITER(112) }

// epilogue for one of the thread's 4 b cells (partition 0 only).
// q=0 -> p1 (x-type N); q=1..4 -> p2..p5 (h-type N)
#define EPI(G, AR, AZ, AN) { \
  ull R = AR, Z = AZ; \
  _Pragma("unroll") \
  for (int q = 0; q < 5; ++q) { \
    const ull* e = red + (size_t)q * 1536 + tid2; \
    add2(R, e[(G) * 128]); add2(Z, e[(4 + (G)) * 128]); } \
  ull X = AN; add2(X, red[(size_t)0 * 1536 + (8 + (G)) * 128 + tid2]); \
  ull Hc = red[(size_t)1 * 1536 + (8 + (G)) * 128 + tid2]; \
  add2(Hc, red[(size_t)2 * 1536 + (8 + (G)) * 128 + tid2]); \
  add2(Hc, red[(size_t)3 * 1536 + (8 + (G)) * 128 + tid2]); \
  add2(Hc, red[(size_t)4 * 1536 + (8 + (G)) * 128 + tid2]); \
  float sR = lof(R) + hif(R), sZ = lof(Z) + hif(Z); \
  float sX = lof(X) + hif(X), sH = lof(Hc) + hif(Hc); \
  float rv = sigf(sR + br), zv = sigf(sZ + bz); \
  float nv = tanf_fast(sX + bn + rv * (sH + bh)); \
  int bq = bb + 16 * (G); \
  float hprev = g_h[d][rs][bq][cb + c]; \
  float hnew = (1.f - zv) * nv + zv * hprev; \
  g_h[d][ws][bq][cb + c] = hnew; \
  out[(size_t)bq * OST + (size_t)t * (2 * Hh) + (size_t)d * Hh + cb + c] = hnew; }

// ---------------- persistent fused BiGRU ----------------
extern "C" __global__ void __launch_bounds__(NTHR, 1)
gru_persist(const float* __restrict__ data,
            const float* __restrict__ Wi_f, const float* __restrict__ bi_f,
            const float* __restrict__ Wh_f, const float* __restrict__ bhn_f,
            const float* __restrict__ Wi_b, const float* __restrict__ bi_b,
            const float* __restrict__ Wh_b, const float* __restrict__ bhn_b,
            float* __restrict__ out) {
    extern __shared__ float smem[];
    float* Ws  = smem;                                        // [24][772]
    ull*   red = (ull*)((char*)smem + WS_BYTES + 4 * VSLOTB); // overlaps h slots

    const int tid = threadIdx.x;
    const int bid = blockIdx.x;
    const int d   = bid >> 6;                 // direction
    const int cb  = (bid & 63) * 8;           // h-column base

    const float* Wi  = d ? Wi_b  : Wi_f;
    const float* Wh  = d ? Wh_b  : Wh_f;
    const float* bi  = d ? bi_b  : bi_f;
    const float* bhn = d ? bhn_b : bhn_f;

    // stage fused weights once: row j = gate*8 + cc, k-major
    for (int idx = tid; idx < 24 * 768; idx += NTHR) {
        int k = idx / 24, j = idx - k * 24;
        int g = j >> 3, cc = j & 7;
        int gcol = g * Hh + cb + cc;
        Ws[j * WSTRIDE + k] = (k < Ff) ? Wi[(size_t)k * (3 * Hh) + gcol]
                                       : Wh[(size_t)(k - Ff) * (3 * Hh) + gcol];
    }

    // zero my 8 h-columns of slot 0
    for (int i = tid; i < Bb * 8; i += NTHR)
        g_h[d][0][i >> 3][cb + (i & 7)] = 0.f;

    // split-K6: partition p handles k in [128p, 128p+128)
    const int p    = tid >> 7;
    const int tid2 = tid & 127;
    const int c    = tid2 >> 4;     // 0..7
    const int bb   = tid2 & 15;     // b base; cells: bb, bb+16, bb+32, bb+48
    const bool isx = (p < 2);       // partition is pure-x (k<256) or pure-h

    const float br = bi[cb + c];
    const float bz = bi[Hh + cb + c];
    const float bn = bi[2 * Hh + cb + c];
    const float bh = bhn[cb + c];

    const unsigned wsA = (unsigned)__cvta_generic_to_shared(Ws);
    const unsigned vsA = (unsigned)__cvta_generic_to_shared((char*)smem + WS_BYTES);
    const unsigned vb0 = (unsigned)(bb        * VROWB);
    const unsigned vb1 = (unsigned)((bb + 16) * VROWB);
    const unsigned vb2 = (unsigned)((bb + 32) * VROWB);
    const unsigned vb3 = (unsigned)((bb + 48) * VROWB);
    const unsigned wrB = wsA + (unsigned)((0  + c) * WSTRIDE) * 4u;
    const unsigned wzB = wsA + (unsigned)((8  + c) * WSTRIDE) * 4u;
    const unsigned wnB = wsA + (unsigned)((16 + c) * WSTRIDE) * 4u;

    const int K0 = p * 128;
    const unsigned slotA = vsA + (unsigned)(2 * p)     * VSLOTB;
    const unsigned slotB = vsA + (unsigned)(2 * p + 1) * VSLOTB;
    const int str = isx ? TFs : Hh;

    // x partitions pre-stage chunks c0,c1 for t=0 (x is constant data)
    if (isx) {
        const float* b0p = data + K0;
        stage32(slotA, b0p,      str, tid2);
        stage32(slotB, b0p + 32, str, tid2);
    }

    grid_barrier(d);   // h zeros + weights visible chip-wide

    // h partitions stage chunks c0,c1 for t=0
    if (!isx) {
        const float* b0p = &g_h[d][0][0][0] + (K0 - Ff);
        stage32(slotA, b0p,      str, tid2);
        stage32(slotB, b0p + 32, str, tid2);
    }

    for (int t = 0; t < Tt; ++t) {
        const int rs = t & 1;
        const int ws = rs ^ 1;
        const float* baseT = isx ? (data + (size_t)t * Ff + K0)
                                 : (&g_h[d][rs][0][0] + (K0 - Ff));
        const int tn = (t + 1 < Tt) ? t + 1 : t;   // clamp (avoid OOB at t=511)
        const float* baseN = data + (size_t)tn * Ff + K0;  // x-next only

        ull aR0=0,aR1=0,aR2=0,aR3=0, aZ0=0,aZ1=0,aZ2=0,aZ3=0;
        ull aN0=0,aN1=0,aN2=0,aN3=0;

        // j0: compute c0 (sA), then stage c2 -> sA
        cpa_wait<1>(); barp(p);
        COMPUTE_CHUNK(slotA, K0);
        barp(p);
        stage32(slotA, baseT + 64, str, tid2);

        // j1: compute c1 (sB), then stage c3 -> sB
        cpa_wait<1>(); barp(p);
        COMPUTE_CHUNK(slotB, K0 + 32);
        barp(p);
        stage32(slotB, baseT + 96, str, tid2);

        // j2: compute c2 (sA); x partitions stage next-step c0' -> sA
        cpa_wait<1>(); barp(p);
        COMPUTE_CHUNK(slotA, K0 + 64);
        barp(p);
        if (isx) stage32(slotA, baseN, TFs, tid2);

        // j3: compute c3 (sB); x partitions stage next-step c1' -> sB
        if (isx) { cpa_wait<1>(); } else { cpa_wait<0>(); }
        barp(p);
        COMPUTE_CHUNK(slotB, K0 + 96);
        if (isx) { barp(p); stage32(slotB, baseN + 32, TFs, tid2); }

        __syncthreads();

        if (p) {   // partitions 1..5 publish partials (conflict-free layout)
            ull* rp = red + (size_t)(p - 1) * 1536 + tid2;
            rp[0*128]=aR0; rp[1*128]=aR1; rp[2*128]=aR2;  rp[3*128]=aR3;
            rp[4*128]=aZ0; rp[5*128]=aZ1; rp[6*128]=aZ2;  rp[7*128]=aZ3;
            rp[8*128]=aN0; rp[9*128]=aN1; rp[10*128]=aN2; rp[11*128]=aN3;
        }
        __syncthreads();

        if (p == 0) {
            EPI(0, aR0, aZ0, aN0)
            EPI(1, aR1, aZ1, aN1)
            EPI(2, aR2, aZ2, aN2)
            EPI(3, aR3, aZ3, aN3)
        }

        grid_barrier(d);

        // h partitions stage chunks c0,c1 for step t+1 (new h now visible)
        if (!isx && t + 1 < Tt) {
            const float* bn2 = &g_h[d][ws][0][0] + (K0 - Ff);
            stage32(slotA, bn2,      str, tid2);
            stage32(slotB, bn2 + 32, str, tid2);
        }
    }
}

extern "C" void kernel_launch(void* const* d_in, const int* in_sizes, int n_in,
                              void* d_out, int out_size) {
    const float* data  = (const float*)d_in[0];
    const float* Wi_f  = (const float*)d_in[1];
    const float* bi_f  = (const float*)d_in[2];
    const float* Wh_f  = (const float*)d_in[3];
    const float* bhn_f = (const float*)d_in[4];
    const float* Wi_b  = (const float*)d_in[5];
    const float* bi_b  = (const float*)d_in[6];
    const float* Wh_b  = (const float*)d_in[7];
    const float* bhn_b = (const float*)d_in[8];
    float* out = (float*)d_out;

    cudaFuncSetAttribute(gru_persist, cudaFuncAttributeMaxDynamicSharedMemorySize, SMEM_BYTES);

    gru_persist<<<GRIDN, NTHR, SMEM_BYTES>>>(data, Wi_f, bi_f, Wh_f, bhn_f,
                                             Wi_b, bi_b, Wh_b, bhn_b, out);
}

// round 10
// speedup vs baseline: 1.1437x; 1.1437x over previous
#include <cuda_runtime.h>
#include <cstdint>
#include <math.h>

#define Bb 64
#define Tt 512
#define Ff 256
#define Hh 512
#define TFs (Tt*Ff)
#define GRIDN 128
#define NTHR 512
#define WSTRIDE 772
#define WS_BYTES (24*WSTRIDE*4)       // 74112
#define VROWB 144                     // 36 floats per b-row (32 data + 4 pad)
#define VSLOTB 9216                   // 64 * 144
#define SMEM_BYTES (WS_BYTES + 16*VSLOTB)   // 221568
#define OST (Tt*2*Hh)

typedef unsigned long long ull;

__device__ float g_h[2][2][Bb][Hh];   // [dir][slot][b][hcol]
__device__ ull   g_barc[32];

// ---------------- helpers ----------------
static __device__ __forceinline__ ull fma2(ull a, ull b, ull c) {
    ull d; asm("fma.rn.f32x2 %0, %1, %2, %3;" : "=l"(d) : "l"(a), "l"(b), "l"(c));
    return d;
}
static __device__ __forceinline__ void add2(ull &a, ull b) {
    asm("add.rn.f32x2 %0, %0, %1;" : "+l"(a) : "l"(b));
}
static __device__ __forceinline__ float lof(ull x) { return __uint_as_float((unsigned)x); }
static __device__ __forceinline__ float hif(ull x) { return __uint_as_float((unsigned)(x >> 32)); }

// volatile is load-bearing (R5/R6 bug: pure asm hoists across barrier asms)
#define LDS128O(base, O, a, b) \
    asm volatile("ld.shared.v2.b64 {%0,%1}, [%2+" #O "];" : "=l"(a), "=l"(b) : "r"(base))

static __device__ __forceinline__ void cpa16(unsigned s, const float4* g) {
    asm volatile("cp.async.cg.shared.global [%0], [%1], 16;"
                 :: "r"(s), "l"(__cvta_generic_to_global((const void*)g)));
}
static __device__ __forceinline__ void cpa_commit() {
    asm volatile("cp.async.commit_group;");
}
template<int N> static __device__ __forceinline__ void cpa_wait() {
    asm volatile("cp.async.wait_group %0;" :: "n"(N) : "memory");
}

static __device__ __forceinline__ float sigf(float x) {
    return __fdividef(1.f, 1.f + __expf(-x));
}
static __device__ __forceinline__ float tanf_fast(float x) {
    return __fdividef(2.f, 1.f + __expf(-2.f * x)) - 1.f;
}

// partition barrier: 64 threads, ids 1..8
static __device__ __forceinline__ void barp(int p) {
    asm volatile("bar.sync %0, 64;" :: "r"(p + 1) : "memory");
}

// per-direction grid barrier (monotonic, graph-replay safe)
static __device__ __forceinline__ void grid_barrier(int d) {
    __threadfence();
    __syncthreads();
    if (threadIdx.x == 0) {
        ull* ctr = &g_barc[d * 16];
        ull old;
        asm volatile("atom.release.gpu.global.add.u64 %0, [%1], 1;"
                     : "=l"(old) : "l"(ctr) : "memory");
        ull target = (old / 64ULL + 1ULL) * 64ULL;
        ull cur = old + 1ULL;
        while (cur < target) {
            asm volatile("ld.acquire.gpu.global.u64 %0, [%1];"
                         : "=l"(cur) : "l"(ctr) : "memory");
            if (cur < target) __nanosleep(20);
        }
        __threadfence();
    }
    __syncthreads();
}

// stage one 32k x 64b chunk (8 KB) with 64 threads (8 cpa16 each)
static __device__ __forceinline__ void stage32(unsigned dst, const float* sb,
                                               int sstr, int t2) {
#pragma unroll
    for (int j = 0; j < 8; ++j) {
        int idx = t2 + j * 64;
        int b = idx >> 3, f = idx & 7;
        cpa16(dst + (unsigned)(b * VROWB + f * 16),
              (const float4*)(sb + (size_t)b * sstr) + f);
    }
    cpa_commit();
}

// 4-k micro-iter: 10 LDS.128, 48 fma.f32x2 (4b x 2c x 3 gates)
#define GITER(O, NT) { \
  ull a0,a1,e0,e1,f0,f1,g0,g1; \
  ull qa0,qa1,qb0,qb1, sa0,sa1,sb0,sb1, wa0,wa1,wb0,wb1; \
  LDS128O(va0,O,a0,a1); LDS128O(va1,O,e0,e1); \
  LDS128O(va2,O,f0,f1); LDS128O(va3,O,g0,g1); \
  LDS128O(xr0,O,qa0,qa1); LDS128O(xr1,O,qb0,qb1); \
  LDS128O(xz0,O,sa0,sa1); LDS128O(xz1,O,sb0,sb1); \
  LDS128O(xn0,O,wa0,wa1); LDS128O(xn1,O,wb0,wb1); \
  R0=fma2(a0,qa0,R0); R0=fma2(a1,qa1,R0); \
  R1=fma2(e0,qa0,R1); R1=fma2(e1,qa1,R1); \
  R2=fma2(f0,qa0,R2); R2=fma2(f1,qa1,R2); \
  R3=fma2(g0,qa0,R3); R3=fma2(g1,qa1,R3); \
  R4=fma2(a0,qb0,R4); R4=fma2(a1,qb1,R4); \
  R5=fma2(e0,qb0,R5); R5=fma2(e1,qb1,R5); \
  R6=fma2(f0,qb0,R6); R6=fma2(f1,qb1,R6); \
  R7=fma2(g0,qb0,R7); R7=fma2(g1,qb1,R7); \
  Z0=fma2(a0,sa0,Z0); Z0=fma2(a1,sa1,Z0); \
  Z1=fma2(e0,sa0,Z1); Z1=fma2(e1,sa1,Z1); \
  Z2=fma2(f0,sa0,Z2); Z2=fma2(f1,sa1,Z2); \
  Z3=fma2(g0,sa0,Z3); Z3=fma2(g1,sa1,Z3); \
  Z4=fma2(a0,sb0,Z4); Z4=fma2(a1,sb1,Z4); \
  Z5=fma2(e0,sb0,Z5); Z5=fma2(e1,sb1,Z5); \
  Z6=fma2(f0,sb0,Z6); Z6=fma2(f1,sb1,Z6); \
  Z7=fma2(g0,sb0,Z7); Z7=fma2(g1,sb1,Z7); \
  NT##0=fma2(a0,wa0,NT##0); NT##0=fma2(a1,wa1,NT##0); \
  NT##1=fma2(e0,wa0,NT##1); NT##1=fma2(e1,wa1,NT##1); \
  NT##2=fma2(f0,wa0,NT##2); NT##2=fma2(f1,wa1,NT##2); \
  NT##3=fma2(g0,wa0,NT##3); NT##3=fma2(g1,wa1,NT##3); \
  NT##4=fma2(a0,wb0,NT##4); NT##4=fma2(a1,wb1,NT##4); \
  NT##5=fma2(e0,wb0,NT##5); NT##5=fma2(e1,wb1,NT##5); \
  NT##6=fma2(f0,wb0,NT##6); NT##6=fma2(f1,wb1,NT##6); \
  NT##7=fma2(g0,wb0,NT##7); NT##7=fma2(g1,wb1,NT##7); }

// 32-k chunk = 8 GITERs
#define COMPUTE_CHUNK(SLOT, KK, NT) { \
  const unsigned va0 = (SLOT) + vb0, va1 = (SLOT) + vb1, \
                 va2 = (SLOT) + vb2, va3 = (SLOT) + vb3; \
  const unsigned xr0 = wr0 + (unsigned)(KK)*4u, xr1 = wr1 + (unsigned)(KK)*4u; \
  const unsigned xz0 = wz0 + (unsigned)(KK)*4u, xz1 = wz1 + (unsigned)(KK)*4u; \
  const unsigned xn0 = wn0 + (unsigned)(KK)*4u, xn1 = wn1 + (unsigned)(KK)*4u; \
  GITER(0,NT)  GITER(16,NT) GITER(32,NT) GITER(48,NT) \
  GITER(64,NT) GITER(80,NT) GITER(96,NT) GITER(112,NT) }

// epilogue: one cell. M = cg*4+g (0..7), MH = half-area index, CG, G compile-time.
#define EPI(M, MH, RR, ZZ, NNA, NNB, CG, G) { \
  ull R = RR, Z = ZZ; \
  add2(R, oth[(0*4 + (MH))*64 + t2]); \
  add2(Z, oth[(1*4 + (MH))*64 + t2]); \
  add2(R, red2[(0*8 + (M))*64 + t2]); \
  add2(Z, red2[(1*8 + (M))*64 + t2]); \
  ull X = NNA; add2(X, NNB); \
  add2(X, oth[(2*4 + (MH))*64 + t2]); \
  add2(X, red2[(2*8 + (M))*64 + t2]); \
  ull Hc = red2nh[(M)*64 + t2]; \
  _Pragma("unroll") \
  for (int q = 0; q < 5; ++q) { \
    const ull* e = red + 3584 + (size_t)q * 1536; \
    add2(R,  e[(0*8 + (M))*64 + t2]); \
    add2(Z,  e[(1*8 + (M))*64 + t2]); \
    add2(Hc, e[(2*8 + (M))*64 + t2]); } \
  float sR = lof(R) + hif(R), sZ = lof(Z) + hif(Z); \
  float sX = lof(X) + hif(X), sH = lof(Hc) + hif(Hc); \
  float brv = (CG) ? br1 : br0, bzv = (CG) ? bz1 : bz0; \
  float bnv = (CG) ? bn1 : bn0, bhv = (CG) ? bh1 : bh0; \
  float rv = sigf(sR + brv), zv = sigf(sZ + bzv); \
  float nv = tanf_fast(sX + bnv + rv * (sH + bhv)); \
  int cc = cg4 + 4 * (CG); \
  int bq = bb + 16 * (G); \
  float hprev = g_h[d][rs][bq][cb + cc]; \
  float hnew = (1.f - zv) * nv + zv * hprev; \
  g_h[d][ws][bq][cb + cc] = hnew; \
  out[(size_t)bq * OST + (size_t)t * (2 * Hh) + (size_t)d * Hh + cb + cc] = hnew; }

// ---------------- persistent fused BiGRU ----------------
extern "C" __global__ void __launch_bounds__(NTHR, 1)
gru_persist(const float* __restrict__ data,
            const float* __restrict__ Wi_f, const float* __restrict__ bi_f,
            const float* __restrict__ Wh_f, const float* __restrict__ bhn_f,
            const float* __restrict__ Wi_b, const float* __restrict__ bi_b,
            const float* __restrict__ Wh_b, const float* __restrict__ bhn_b,
            float* __restrict__ out) {
    extern __shared__ float smem[];
    float* Ws = smem;                                        // [24][772]
    ull* red  = (ull*)((char*)smem + WS_BYTES + 6 * VSLOTB); // overlays p3..p7 slots

    const int tid = threadIdx.x;
    const int bid = blockIdx.x;
    const int d   = bid >> 6;
    const int cb  = (bid & 63) * 8;

    const float* Wi  = d ? Wi_b  : Wi_f;
    const float* Wh  = d ? Wh_b  : Wh_f;
    const float* bi  = d ? bi_b  : bi_f;
    const float* bhn = d ? bhn_b : bhn_f;

    // stage fused weights once (row j = gate*8+cc, k-major)
    for (int idx = tid; idx < 24 * 768; idx += NTHR) {
        int k = idx / 24, j = idx - k * 24;
        int g = j >> 3, cc = j & 7;
        int gcol = g * Hh + cb + cc;
        Ws[j * WSTRIDE + k] = (k < Ff) ? Wi[(size_t)k * (3 * Hh) + gcol]
                                       : Wh[(size_t)(k - Ff) * (3 * Hh) + gcol];
    }
    for (int i = tid; i < Bb * 8; i += NTHR)
        g_h[d][0][i >> 3][cb + (i & 7)] = 0.f;

    // 8 partitions x 64 threads; partition p: k in [96p, 96p+96)
    const int p   = tid >> 6;
    const int t2  = tid & 63;
    const int bb  = t2 & 15;       // b base: cells bb, +16, +32, +48
    const int cg4 = t2 >> 4;       // 0..3: c-pair {cg4, cg4+4}
    const bool c01x = (p <= 2);    // chunks c0,c1 are x-type

    const float br0 = bi[cb + cg4],          br1 = bi[cb + cg4 + 4];
    const float bz0 = bi[Hh + cb + cg4],     bz1 = bi[Hh + cb + cg4 + 4];
    const float bn0 = bi[2 * Hh + cb + cg4], bn1 = bi[2 * Hh + cb + cg4 + 4];
    const float bh0 = bhn[cb + cg4],         bh1 = bhn[cb + cg4 + 4];

    const unsigned wsA = (unsigned)__cvta_generic_to_shared(Ws);
    const unsigned vsA = (unsigned)__cvta_generic_to_shared((char*)smem + WS_BYTES);
    const unsigned vb0 = (unsigned)(bb        * VROWB);
    const unsigned vb1 = (unsigned)((bb + 16) * VROWB);
    const unsigned vb2 = (unsigned)((bb + 32) * VROWB);
    const unsigned vb3 = (unsigned)((bb + 48) * VROWB);
    const unsigned wr0 = wsA + (unsigned)((0  + cg4)     * WSTRIDE) * 4u;
    const unsigned wr1 = wsA + (unsigned)((0  + cg4 + 4) * WSTRIDE) * 4u;
    const unsigned wz0 = wsA + (unsigned)((8  + cg4)     * WSTRIDE) * 4u;
    const unsigned wz1 = wsA + (unsigned)((8  + cg4 + 4) * WSTRIDE) * 4u;
    const unsigned wn0 = wsA + (unsigned)((16 + cg4)     * WSTRIDE) * 4u;
    const unsigned wn1 = wsA + (unsigned)((16 + cg4 + 4) * WSTRIDE) * 4u;

    const int K0 = p * 96;
    unsigned SA = vsA + (unsigned)(2 * p)     * VSLOTB;
    unsigned SB = vsA + (unsigned)(2 * p + 1) * VSLOTB;

    // x partitions prestage t=0 chunks c0,c1
    if (c01x) {
        stage32(SA, data + K0,      TFs, t2);
        stage32(SB, data + K0 + 32, TFs, t2);
    }
    grid_barrier(d);
    if (!c01x) {
        const float* hb = &g_h[d][0][0][0];
        stage32(SA, hb + (K0 - Ff),      Hh, t2);
        stage32(SB, hb + (K0 + 32 - Ff), Hh, t2);
    }

    for (int t = 0; t < Tt; ++t) {
        const int rs = t & 1;
        const int ws = rs ^ 1;
        const float* hb = &g_h[d][rs][0][0];
        const int k2 = K0 + 64;
        const float* src2 = (k2 < Ff) ? (data + (size_t)t * Ff + k2) : (hb + (k2 - Ff));
        const int str2 = (k2 < Ff) ? TFs : Hh;
        const int tn = (t + 1 < Tt) ? t + 1 : t;
        const float* xn_ = data + (size_t)tn * Ff + K0;

        ull R0=0,R1=0,R2=0,R3=0,R4=0,R5=0,R6=0,R7=0;
        ull Z0=0,Z1=0,Z2=0,Z3=0,Z4=0,Z5=0,Z6=0,Z7=0;
        ull NA0=0,NA1=0,NA2=0,NA3=0,NA4=0,NA5=0,NA6=0,NA7=0;
        ull NB0=0,NB1=0,NB2=0,NB3=0,NB4=0,NB5=0,NB6=0,NB7=0;

        cpa_wait<1>(); barp(p);
        COMPUTE_CHUNK(SA, K0, NA);
        barp(p);
        stage32(SA, src2, str2, t2);

        cpa_wait<1>(); barp(p);
        COMPUTE_CHUNK(SB, K0 + 32, NA);
        barp(p);
        if (c01x) stage32(SB, xn_, TFs, t2);

        if (c01x) { cpa_wait<1>(); } else { cpa_wait<0>(); }
        barp(p);
        COMPUTE_CHUNK(SA, K0 + 64, NB);
        barp(p);
        if (c01x) stage32(SA, xn_ + 32, TFs, t2);

        __syncthreads();

        // publish partials
        if (p == 0) {                       // cells {2,3,6,7} only (g 2,3)
            ull* a = red;
            a[(0*4+0)*64+t2]=R2; a[(0*4+1)*64+t2]=R3; a[(0*4+2)*64+t2]=R6; a[(0*4+3)*64+t2]=R7;
            a[(1*4+0)*64+t2]=Z2; a[(1*4+1)*64+t2]=Z3; a[(1*4+2)*64+t2]=Z6; a[(1*4+3)*64+t2]=Z7;
            ull n2=NA2; add2(n2,NB2); ull n3=NA3; add2(n3,NB3);
            ull n6=NA6; add2(n6,NB6); ull n7=NA7; add2(n7,NB7);
            a[(2*4+0)*64+t2]=n2; a[(2*4+1)*64+t2]=n3; a[(2*4+2)*64+t2]=n6; a[(2*4+3)*64+t2]=n7;
        } else if (p == 1) {                // cells {0,1,4,5}
            ull* a = red + 768;
            a[(0*4+0)*64+t2]=R0; a[(0*4+1)*64+t2]=R1; a[(0*4+2)*64+t2]=R4; a[(0*4+3)*64+t2]=R5;
            a[(1*4+0)*64+t2]=Z0; a[(1*4+1)*64+t2]=Z1; a[(1*4+2)*64+t2]=Z4; a[(1*4+3)*64+t2]=Z5;
            ull n0=NA0; add2(n0,NB0); ull n1=NA1; add2(n1,NB1);
            ull n4=NA4; add2(n4,NB4); ull n5=NA5; add2(n5,NB5);
            a[(2*4+0)*64+t2]=n0; a[(2*4+1)*64+t2]=n1; a[(2*4+2)*64+t2]=n4; a[(2*4+3)*64+t2]=n5;
        } else if (p == 2) {                // NX=NA (k<256), NH=NB (k=256..288)
            ull* a = red + 1536;
            a[(0*8+0)*64+t2]=R0; a[(0*8+1)*64+t2]=R1; a[(0*8+2)*64+t2]=R2; a[(0*8+3)*64+t2]=R3;
            a[(0*8+4)*64+t2]=R4; a[(0*8+5)*64+t2]=R5; a[(0*8+6)*64+t2]=R6; a[(0*8+7)*64+t2]=R7;
            a[(1*8+0)*64+t2]=Z0; a[(1*8+1)*64+t2]=Z1; a[(1*8+2)*64+t2]=Z2; a[(1*8+3)*64+t2]=Z3;
            a[(1*8+4)*64+t2]=Z4; a[(1*8+5)*64+t2]=Z5; a[(1*8+6)*64+t2]=Z6; a[(1*8+7)*64+t2]=Z7;
            a[(2*8+0)*64+t2]=NA0; a[(2*8+1)*64+t2]=NA1; a[(2*8+2)*64+t2]=NA2; a[(2*8+3)*64+t2]=NA3;
            a[(2*8+4)*64+t2]=NA4; a[(2*8+5)*64+t2]=NA5; a[(2*8+6)*64+t2]=NA6; a[(2*8+7)*64+t2]=NA7;
            ull* b2 = red + 3072;
            b2[0*64+t2]=NB0; b2[1*64+t2]=NB1; b2[2*64+t2]=NB2; b2[3*64+t2]=NB3;
            b2[4*64+t2]=NB4; b2[5*64+t2]=NB5; b2[6*64+t2]=NB6; b2[7*64+t2]=NB7;
        } else {                            // h partitions: N merged
            ull* a = red + 3584 + (size_t)(p - 3) * 1536;
            a[(0*8+0)*64+t2]=R0; a[(0*8+1)*64+t2]=R1; a[(0*8+2)*64+t2]=R2; a[(0*8+3)*64+t2]=R3;
            a[(0*8+4)*64+t2]=R4; a[(0*8+5)*64+t2]=R5; a[(0*8+6)*64+t2]=R6; a[(0*8+7)*64+t2]=R7;
            a[(1*8+0)*64+t2]=Z0; a[(1*8+1)*64+t2]=Z1; a[(1*8+2)*64+t2]=Z2; a[(1*8+3)*64+t2]=Z3;
            a[(1*8+4)*64+t2]=Z4; a[(1*8+5)*64+t2]=Z5; a[(1*8+6)*64+t2]=Z6; a[(1*8+7)*64+t2]=Z7;
            ull n0=NA0; add2(n0,NB0); ull n1=NA1; add2(n1,NB1);
            ull n2=NA2; add2(n2,NB2); ull n3=NA3; add2(n3,NB3);
            ull n4=NA4; add2(n4,NB4); ull n5=NA5; add2(n5,NB5);
            ull n6=NA6; add2(n6,NB6); ull n7=NA7; add2(n7,NB7);
            a[(2*8+0)*64+t2]=n0; a[(2*8+1)*64+t2]=n1; a[(2*8+2)*64+t2]=n2; a[(2*8+3)*64+t2]=n3;
            a[(2*8+4)*64+t2]=n4; a[(2*8+5)*64+t2]=n5; a[(2*8+6)*64+t2]=n6; a[(2*8+7)*64+t2]=n7;
        }
        __syncthreads();

        if (p == 0) {       // finalize cells g in {0,1}; own regs, p1's half-area
            const ull* oth = red + 768;
            const ull* red2 = red + 1536;
            const ull* red2nh = red + 3072;
            EPI(0, 0, R0, Z0, NA0, NB0, 0, 0)
            EPI(1, 1, R1, Z1, NA1, NB1, 0, 1)
            EPI(4, 2, R4, Z4, NA4, NB4, 1, 0)
            EPI(5, 3, R5, Z5, NA5, NB5, 1, 1)
        } else if (p == 1) { // finalize cells g in {2,3}; own regs, p0's half-area
            const ull* oth = red;
            const ull* red2 = red + 1536;
            const ull* red2nh = red + 3072;
            EPI(2, 0, R2, Z2, NA2, NB2, 0, 2)
            EPI(3, 1, R3, Z3, NA3, NB3, 0, 3)
            EPI(6, 2, R6, Z6, NA6, NB6, 1, 2)
            EPI(7, 3, R7, Z7, NA7, NB7, 1, 3)
        }

        grid_barrier(d);

        if (!c01x && t + 1 < Tt) {
            const float* hb2 = &g_h[d][ws][0][0];
            stage32(SB, hb2 + (K0 - Ff),      Hh, t2);
            stage32(SA, hb2 + (K0 + 32 - Ff), Hh, t2);
        }
        unsigned tmp = SA; SA = SB; SB = tmp;
    }
}

extern "C" void kernel_launch(void* const* d_in, const int* in_sizes, int n_in,
                              void* d_out, int out_size) {
    const float* data  = (const float*)d_in[0];
    const float* Wi_f  = (const float*)d_in[1];
    const float* bi_f  = (const float*)d_in[2];
    const float* Wh_f  = (const float*)d_in[3];
    const float* bhn_f = (const float*)d_in[4];
    const float* Wi_b  = (const float*)d_in[5];
    const float* bi_b  = (const float*)d_in[6];
    const float* Wh_b  = (const float*)d_in[7];
    const float* bhn_b = (const float*)d_in[8];
    float* out = (float*)d_out;

    cudaFuncSetAttribute(gru_persist, cudaFuncAttributeMaxDynamicSharedMemorySize, SMEM_BYTES);

    gru_persist<<<GRIDN, NTHR, SMEM_BYTES>>>(data, Wi_f, bi_f, Wh_f, bhn_f,
                                             Wi_b, bi_b, Wh_b, bhn_b, out);
}

// round 11
// speedup vs baseline: 1.1633x; 1.0172x over previous
#include <cuda_runtime.h>
#include <cstdint>
#include <math.h>

#define Bb 64
#define Tt 512
#define Ff 256
#define Hh 512
#define TFs (Tt*Ff)
#define GRIDN 128
#define NTHR 512
#define WSTRIDE 772
#define WS_BYTES (24*WSTRIDE*4)        // 74112
#define VROWB 144                      // 36 floats per b-row (32 data + 4 pad)
#define VSLOTB 9216                    // 64 * 144
#define XG_BYTES 6144                  // 1536 floats staged xg
#define SMEM_BYTES (WS_BYTES + 16*VSLOTB + XG_BYTES)   // 227712
#define OST (Tt*2*Hh)
#define REDP 2304                      // ull per partition red region (2*VSLOTB/8)

typedef unsigned long long ull;

__device__ float g_h[2][2][Bb][Hh];        // [dir][slot][b][hcol]
__device__ float g_xg[GRIDN][Tt][1536];    // precomputed x-gates (+bi), per block
__device__ ull   g_barc[32];

// ---------------- helpers ----------------
static __device__ __forceinline__ ull fma2(ull a, ull b, ull c) {
    ull d; asm("fma.rn.f32x2 %0, %1, %2, %3;" : "=l"(d) : "l"(a), "l"(b), "l"(c));
    return d;
}
static __device__ __forceinline__ void add2(ull &a, ull b) {
    asm("add.rn.f32x2 %0, %0, %1;" : "+l"(a) : "l"(b));
}
static __device__ __forceinline__ float lof(ull x) { return __uint_as_float((unsigned)x); }
static __device__ __forceinline__ float hif(ull x) { return __uint_as_float((unsigned)(x >> 32)); }

// volatile is load-bearing (R5/R6 bug: pure asm hoists across barrier asms)
#define LDS128O(base, O, a, b) \
    asm volatile("ld.shared.v2.b64 {%0,%1}, [%2+" #O "];" : "=l"(a), "=l"(b) : "r"(base))

static __device__ __forceinline__ void cpa16(unsigned s, const float4* g) {
    asm volatile("cp.async.cg.shared.global [%0], [%1], 16;"
                 :: "r"(s), "l"(__cvta_generic_to_global((const void*)g)));
}
static __device__ __forceinline__ void cpa_commit() {
    asm volatile("cp.async.commit_group;");
}
template<int N> static __device__ __forceinline__ void cpa_wait() {
    asm volatile("cp.async.wait_group %0;" :: "n"(N) : "memory");
}

static __device__ __forceinline__ float sigf(float x) {
    return __fdividef(1.f, 1.f + __expf(-x));
}
static __device__ __forceinline__ float tanf_fast(float x) {
    return __fdividef(2.f, 1.f + __expf(-2.f * x)) - 1.f;
}

// partition barrier: 64 threads, ids 1..8 ("memory" clobber = compiler fence)
static __device__ __forceinline__ void barp(int p) {
    asm volatile("bar.sync %0, 64;" :: "r"(p + 1) : "memory");
}

// per-direction grid barrier (monotonic counter, graph-replay safe)
static __device__ __forceinline__ void grid_barrier(int d) {
    __threadfence();
    __syncthreads();
    if (threadIdx.x == 0) {
        ull* ctr = &g_barc[d * 16];
        ull old;
        asm volatile("atom.release.gpu.global.add.u64 %0, [%1], 1;"
                     : "=l"(old) : "l"(ctr) : "memory");
        ull target = (old / 64ULL + 1ULL) * 64ULL;
        ull cur = old + 1ULL;
        while (cur < target) {
            asm volatile("ld.acquire.gpu.global.u64 %0, [%1];"
                         : "=l"(cur) : "l"(ctr) : "memory");
            if (cur < target) __nanosleep(20);
        }
        __threadfence();
    }
    __syncthreads();
}

// stage one 32k x 64b chunk (8 KB); 8 cp.async per thread; NO commit
static __device__ __forceinline__ void stage32(unsigned dst, const float* sb,
                                               int sstr, int t2) {
#pragma unroll
    for (int j = 0; j < 8; ++j) {
        int idx = t2 + j * 64;
        int b = idx >> 3, f = idx & 7;
        cpa16(dst + (unsigned)(b * VROWB + f * 16),
              (const float4*)(sb + (size_t)b * sstr) + f);
    }
}

// 4-k micro-iter: 10 LDS.128, 48 fma.f32x2 (4b x 2c x 3 gates)
#define GITER(O) { \
  ull a0,a1,e0,e1,f0,f1,g0,g1; \
  ull qa0,qa1,qb0,qb1, sa0,sa1,sb0,sb1, wa0,wa1,wb0,wb1; \
  LDS128O(va0,O,a0,a1); LDS128O(va1,O,e0,e1); \
  LDS128O(va2,O,f0,f1); LDS128O(va3,O,g0,g1); \
  LDS128O(xr0,O,qa0,qa1); LDS128O(xr1,O,qb0,qb1); \
  LDS128O(xz0,O,sa0,sa1); LDS128O(xz1,O,sb0,sb1); \
  LDS128O(xn0,O,wa0,wa1); LDS128O(xn1,O,wb0,wb1); \
  R0=fma2(a0,qa0,R0); R0=fma2(a1,qa1,R0); \
  R1=fma2(e0,qa0,R1); R1=fma2(e1,qa1,R1); \
  R2=fma2(f0,qa0,R2); R2=fma2(f1,qa1,R2); \
  R3=fma2(g0,qa0,R3); R3=fma2(g1,qa1,R3); \
  R4=fma2(a0,qb0,R4); R4=fma2(a1,qb1,R4); \
  R5=fma2(e0,qb0,R5); R5=fma2(e1,qb1,R5); \
  R6=fma2(f0,qb0,R6); R6=fma2(f1,qb1,R6); \
  R7=fma2(g0,qb0,R7); R7=fma2(g1,qb1,R7); \
  Z0=fma2(a0,sa0,Z0); Z0=fma2(a1,sa1,Z0); \
  Z1=fma2(e0,sa0,Z1); Z1=fma2(e1,sa1,Z1); \
  Z2=fma2(f0,sa0,Z2); Z2=fma2(f1,sa1,Z2); \
  Z3=fma2(g0,sa0,Z3); Z3=fma2(g1,sa1,Z3); \
  Z4=fma2(a0,sb0,Z4); Z4=fma2(a1,sb1,Z4); \
  Z5=fma2(e0,sb0,Z5); Z5=fma2(e1,sb1,Z5); \
  Z6=fma2(f0,sb0,Z6); Z6=fma2(f1,sb1,Z6); \
  Z7=fma2(g0,sb0,Z7); Z7=fma2(g1,sb1,Z7); \
  N0=fma2(a0,wa0,N0); N0=fma2(a1,wa1,N0); \
  N1=fma2(e0,wa0,N1); N1=fma2(e1,wa1,N1); \
  N2=fma2(f0,wa0,N2); N2=fma2(f1,wa1,N2); \
  N3=fma2(g0,wa0,N3); N3=fma2(g1,wa1,N3); \
  N4=fma2(a0,wb0,N4); N4=fma2(a1,wb1,N4); \
  N5=fma2(e0,wb0,N5); N5=fma2(e1,wb1,N5); \
  N6=fma2(f0,wb0,N6); N6=fma2(f1,wb1,N6); \
  N7=fma2(g0,wb0,N7); N7=fma2(g1,wb1,N7); }

// 32-k chunk = 8 GITERs
#define COMPUTE_CHUNK(SLOT, KK) { \
  const unsigned va0 = (SLOT) + vb0, va1 = (SLOT) + vb1, \
                 va2 = (SLOT) + vb2, va3 = (SLOT) + vb3; \
  const unsigned xr0 = wr0 + (unsigned)(KK)*4u, xr1 = wr1 + (unsigned)(KK)*4u; \
  const unsigned xz0 = wz0 + (unsigned)(KK)*4u, xz1 = wz1 + (unsigned)(KK)*4u; \
  const unsigned xn0 = wn0 + (unsigned)(KK)*4u, xn1 = wn1 + (unsigned)(KK)*4u; \
  GITER(0)  GITER(16) GITER(32) GITER(48) \
  GITER(64) GITER(80) GITER(96) GITER(112) }

// phase-1 store: cell (CG,G) of gate GA, bias folded
#define P1ST(ACC, GA, CG, G, BI) \
  xgrow[((GA)*8 + cg4 + 4*(CG))*64 + bb + 16*(G)] = lof(ACC) + hif(ACC) + (BI);

// ---------------- persistent fused BiGRU ----------------
extern "C" __global__ void __launch_bounds__(NTHR, 1)
gru_persist(const float* __restrict__ data,
            const float* __restrict__ Wi_f, const float* __restrict__ bi_f,
            const float* __restrict__ Wh_f, const float* __restrict__ bhn_f,
            const float* __restrict__ Wi_b, const float* __restrict__ bi_b,
            const float* __restrict__ Wh_b, const float* __restrict__ bhn_b,
            float* __restrict__ out) {
    extern __shared__ float smem[];
    float* Ws   = smem;                                    // [24][772]
    ull* redAll = (ull*)((char*)smem + WS_BYTES);          // overlays the 16 slots

    const int tid = threadIdx.x;
    const int bid = blockIdx.x;
    const int d   = bid >> 6;
    const int cb  = (bid & 63) * 8;

    const float* Wi  = d ? Wi_b  : Wi_f;
    const float* Wh  = d ? Wh_b  : Wh_f;
    const float* bi  = d ? bi_b  : bi_f;
    const float* bhn = d ? bhn_b : bhn_f;

    // stage fused weights once (row j = gate*8+cc; k<256 Wi, k>=256 Wh)
    for (int idx = tid; idx < 24 * 768; idx += NTHR) {
        int k = idx / 24, j = idx - k * 24;
        int g = j >> 3, cc = j & 7;
        int gcol = g * Hh + cb + cc;
        Ws[j * WSTRIDE + k] = (k < Ff) ? Wi[(size_t)k * (3 * Hh) + gcol]
                                       : Wh[(size_t)(k - Ff) * (3 * Hh) + gcol];
    }
    for (int i = tid; i < Bb * 8; i += NTHR)
        g_h[d][0][i >> 3][cb + (i & 7)] = 0.f;

    // 8 partitions x 64 threads
    const int p   = tid >> 6;
    const int t2  = tid & 63;
    const int bb  = t2 & 15;
    const int cg4 = t2 >> 4;

    // distributed-epilogue cell mapping: cell m = tid
    const int eM  = tid >> 6, et2 = tid & 63;
    const int ebq = (et2 & 15) + 16 * (eM & 3);
    const int ecc = (et2 >> 4) + 4 * (eM >> 2);
    const float ebh = bhn[cb + ecc];

    // phase-1 biases (folded into xg)
    const float bi00 = bi[cb + cg4],          bi01 = bi[cb + cg4 + 4];
    const float bi10 = bi[Hh + cb + cg4],     bi11 = bi[Hh + cb + cg4 + 4];
    const float bi20 = bi[2*Hh + cb + cg4],   bi21 = bi[2*Hh + cb + cg4 + 4];

    const unsigned wsA = (unsigned)__cvta_generic_to_shared(Ws);
    const unsigned vsA = (unsigned)__cvta_generic_to_shared((char*)smem + WS_BYTES);
    const unsigned xgA = vsA + 16u * VSLOTB;
    const unsigned vb0 = (unsigned)(bb        * VROWB);
    const unsigned vb1 = (unsigned)((bb + 16) * VROWB);
    const unsigned vb2 = (unsigned)((bb + 32) * VROWB);
    const unsigned vb3 = (unsigned)((bb + 48) * VROWB);
    const unsigned wr0 = wsA + (unsigned)((0  + cg4)     * WSTRIDE) * 4u;
    const unsigned wr1 = wsA + (unsigned)((0  + cg4 + 4) * WSTRIDE) * 4u;
    const unsigned wz0 = wsA + (unsigned)((8  + cg4)     * WSTRIDE) * 4u;
    const unsigned wz1 = wsA + (unsigned)((8  + cg4 + 4) * WSTRIDE) * 4u;
    const unsigned wn0 = wsA + (unsigned)((16 + cg4)     * WSTRIDE) * 4u;
    const unsigned wn1 = wsA + (unsigned)((16 + cg4 + 4) * WSTRIDE) * 4u;

    const unsigned SA = vsA + (unsigned)(2 * p)     * VSLOTB;
    const unsigned SB = vsA + (unsigned)(2 * p + 1) * VSLOTB;
    const int K0h = p * 64;     // phase-2 h k-range

    // ================= PHASE 1: xg = x @ Wi + bi (partition p owns t = 8j+p) =================
    stage32(SA, data + (size_t)p * Ff,      TFs, t2); cpa_commit();
    stage32(SB, data + (size_t)p * Ff + 32, TFs, t2); cpa_commit();

    for (int jt = 0; jt < 64; ++jt) {
        const int t = 8 * jt + p;
        ull R0=0,R1=0,R2=0,R3=0,R4=0,R5=0,R6=0,R7=0;
        ull Z0=0,Z1=0,Z2=0,Z3=0,Z4=0,Z5=0,Z6=0,Z7=0;
        ull N0=0,N1=0,N2=0,N3=0,N4=0,N5=0,N6=0,N7=0;

        #pragma unroll 1
        for (int j = 0; j < 8; ++j) {
            if (jt == 63 && j == 7) { cpa_wait<0>(); } else { cpa_wait<1>(); }
            barp(p);
            COMPUTE_CHUNK((j & 1) ? SB : SA, 32 * j);
            barp(p);
            if (jt < 63 || j < 6) {
                const int tS = (j < 6) ? t : t + 8;
                const int kS = ((j + 2) & 7) * 32;
                stage32((j & 1) ? SB : SA, data + (size_t)tS * Ff + kS, TFs, t2);
                cpa_commit();
            }
        }

        float* xgrow = &g_xg[bid][t][0];
        P1ST(R0,0,0,0,bi00) P1ST(R1,0,0,1,bi00) P1ST(R2,0,0,2,bi00) P1ST(R3,0,0,3,bi00)
        P1ST(R4,0,1,0,bi01) P1ST(R5,0,1,1,bi01) P1ST(R6,0,1,2,bi01) P1ST(R7,0,1,3,bi01)
        P1ST(Z0,1,0,0,bi10) P1ST(Z1,1,0,1,bi10) P1ST(Z2,1,0,2,bi10) P1ST(Z3,1,0,3,bi10)
        P1ST(Z4,1,1,0,bi11) P1ST(Z5,1,1,1,bi11) P1ST(Z6,1,1,2,bi11) P1ST(Z7,1,1,3,bi11)
        P1ST(N0,2,0,0,bi20) P1ST(N1,2,0,1,bi20) P1ST(N2,2,0,2,bi20) P1ST(N3,2,0,3,bi20)
        P1ST(N4,2,1,0,bi21) P1ST(N5,2,1,1,bi21) P1ST(N6,2,1,2,bi21) P1ST(N7,2,1,3,bi21)
    }

    grid_barrier(d);   // xg + h zeros + weights visible chip-wide

    // ================= PHASE 2: recurrence over h (K=512 split 8x64) =================
    {   // initial stage for t=0: c0 (+xg(0) bundled into p0's first group), c1
        const float* hb = &g_h[d][0][0][0];
        stage32(SA, hb + K0h, Hh, t2);
        if (p == 0) {
            const float4* xs = (const float4*)&g_xg[bid][0][0];
            #pragma unroll
            for (int i = 0; i < 6; ++i)
                cpa16(xgA + (unsigned)((t2 + i * 64) * 16), xs + t2 + i * 64);
        }
        cpa_commit();
        stage32(SB, hb + K0h + 32, Hh, t2);
        cpa_commit();
    }

    for (int t = 0; t < Tt; ++t) {
        const int rs = t & 1;
        const int ws = rs ^ 1;

        ull R0=0,R1=0,R2=0,R3=0,R4=0,R5=0,R6=0,R7=0;
        ull Z0=0,Z1=0,Z2=0,Z3=0,Z4=0,Z5=0,Z6=0,Z7=0;
        ull N0=0,N1=0,N2=0,N3=0,N4=0,N5=0,N6=0,N7=0;

        #pragma unroll 1
        for (int j = 0; j < 2; ++j) {
            if (j == 0) { cpa_wait<1>(); } else { cpa_wait<0>(); }
            barp(p);
            COMPUTE_CHUNK(j ? SB : SA, 256 + K0h + 32 * j);
        }
        barp(p);   // all partition threads done reading slots (also compiler fence)

        // publish into OWN slot region (no cross-partition WAR)
        {
            ull* rp = redAll + (size_t)p * REDP;
            rp[0*512 + 0*64 + t2] = R0; rp[0*512 + 1*64 + t2] = R1;
            rp[0*512 + 2*64 + t2] = R2; rp[0*512 + 3*64 + t2] = R3;
            rp[0*512 + 4*64 + t2] = R4; rp[0*512 + 5*64 + t2] = R5;
            rp[0*512 + 6*64 + t2] = R6; rp[0*512 + 7*64 + t2] = R7;
            rp[1*512 + 0*64 + t2] = Z0; rp[1*512 + 1*64 + t2] = Z1;
            rp[1*512 + 2*64 + t2] = Z2; rp[1*512 + 3*64 + t2] = Z3;
            rp[1*512 + 4*64 + t2] = Z4; rp[1*512 + 5*64 + t2] = Z5;
            rp[1*512 + 6*64 + t2] = Z6; rp[1*512 + 7*64 + t2] = Z7;
            rp[2*512 + 0*64 + t2] = N0; rp[2*512 + 1*64 + t2] = N1;
            rp[2*512 + 2*64 + t2] = N2; rp[2*512 + 3*64 + t2] = N3;
            rp[2*512 + 4*64 + t2] = N4; rp[2*512 + 5*64 + t2] = N5;
            rp[2*512 + 6*64 + t2] = N6; rp[2*512 + 7*64 + t2] = N7;
        }
        __syncthreads();

        // distributed epilogue: every thread finalizes cell m = tid
        {
            ull Rm = 0, Zm = 0, Nm = 0;
            #pragma unroll
            for (int q = 0; q < 8; ++q) {
                const ull* e = redAll + (size_t)q * REDP;
                add2(Rm, e[tid]); add2(Zm, e[512 + tid]); add2(Nm, e[1024 + tid]);
            }
            const float* xgS = (const float*)((char*)smem + WS_BYTES + 16 * VSLOTB);
            float xr = xgS[(0*8 + ecc) * 64 + ebq];
            float xz = xgS[(1*8 + ecc) * 64 + ebq];
            float xn = xgS[(2*8 + ecc) * 64 + ebq];
            float hprev = g_h[d][rs][ebq][cb + ecc];
            float sR = lof(Rm) + hif(Rm);
            float sZ = lof(Zm) + hif(Zm);
            float sN = lof(Nm) + hif(Nm);
            float rv = sigf(xr + sR);
            float zv = sigf(xz + sZ);
            float nv = tanf_fast(xn + rv * (sN + ebh));
            float hnew = (1.f - zv) * nv + zv * hprev;
            g_h[d][ws][ebq][cb + ecc] = hnew;
            out[(size_t)ebq * OST + (size_t)t * (2 * Hh) + (size_t)d * Hh + cb + ecc] = hnew;
        }

        grid_barrier(d);

        if (t + 1 < Tt) {
            const float* hb = &g_h[d][ws][0][0];
            stage32(SA, hb + K0h, Hh, t2);
            if (p == 0) {
                const float4* xs = (const float4*)&g_xg[bid][t + 1][0];
                #pragma unroll
                for (int i = 0; i < 6; ++i)
                    cpa16(xgA + (unsigned)((t2 + i * 64) * 16), xs + t2 + i * 64);
            }
            cpa_commit();
            stage32(SB, hb + K0h + 32, Hh, t2);
            cpa_commit();
        }
    }
}

extern "C" void kernel_launch(void* const* d_in, const int* in_sizes, int n_in,
                              void* d_out, int out_size) {
    const float* data  = (const float*)d_in[0];
    const float* Wi_f  = (const float*)d_in[1];
    const float* bi_f  = (const float*)d_in[2];
    const float* Wh_f  = (const float*)d_in[3];
    const float* bhn_f = (const float*)d_in[4];
    const float* Wi_b  = (const float*)d_in[5];
    const float* bi_b  = (const float*)d_in[6];
    const float* Wh_b  = (const float*)d_in[7];
    const float* bhn_b = (const float*)d_in[8];
    float* out = (float*)d_out;

    cudaFuncSetAttribute(gru_persist, cudaFuncAttributeMaxDynamicSharedMemorySize, SMEM_BYTES);

    gru_persist<<<GRIDN, NTHR, SMEM_BYTES>>>(data, Wi_f, bi_f, Wh_f, bhn_f,
                                             Wi_b, bi_b, Wh_b, bhn_b, out);
}

// round 12
// speedup vs baseline: 1.2794x; 1.0998x over previous
#include <cuda_runtime.h>
#include <cstdint>
#include <math.h>

#define Bb 64
#define Tt 512
#define Ff 256
#define Hh 512
#define TFs (Tt*Ff)
#define GRIDN 128
#define NTHR 512
#define WSTRIDE 772
#define WS_BYTES (24*WSTRIDE*4)        // 74112
// phase-1 slots (old layout)
#define VROWB 144
#define VSLOTB 9216
// phase-2 slots (kp layout): 16 kp-rows x 512B
#define VSLOTB2 8192
#define XG_BYTES 6144
#define SMEM_BYTES (WS_BYTES + 16*VSLOTB)   // 221568 (phase-1 region governs)
#define OST (Tt*2*Hh)

typedef unsigned long long ull;

__device__ float g_h[2][2][Hh/2][Bb][2];   // [dir][slot][kpair][b][parity]
__device__ float g_xg[GRIDN][Tt][1536];    // precomputed x-gates (+bi), per block
__device__ ull   g_barc[32];

// ---------------- helpers ----------------
static __device__ __forceinline__ ull fma2(ull a, ull b, ull c) {
    ull d; asm("fma.rn.f32x2 %0, %1, %2, %3;" : "=l"(d) : "l"(a), "l"(b), "l"(c));
    return d;
}
static __device__ __forceinline__ void add2(ull &a, ull b) {
    asm("add.rn.f32x2 %0, %0, %1;" : "+l"(a) : "l"(b));
}
static __device__ __forceinline__ float lof(ull x) { return __uint_as_float((unsigned)x); }
static __device__ __forceinline__ float hif(ull x) { return __uint_as_float((unsigned)(x >> 32)); }

// volatile is load-bearing (R5/R6 bug: pure asm hoists across barrier asms)
#define LDS128O(base, O, a, b) \
    asm volatile("ld.shared.v2.b64 {%0,%1}, [%2+" #O "];" : "=l"(a), "=l"(b) : "r"(base))
#define LDS64O(base, O, a) \
    asm volatile("ld.shared.b64 %0, [%1+" #O "];" : "=l"(a) : "r"(base))

static __device__ __forceinline__ void cpa16(unsigned s, const float4* g) {
    asm volatile("cp.async.cg.shared.global [%0], [%1], 16;"
                 :: "r"(s), "l"(__cvta_generic_to_global((const void*)g)));
}
static __device__ __forceinline__ void cpa_commit() {
    asm volatile("cp.async.commit_group;");
}
template<int N> static __device__ __forceinline__ void cpa_wait() {
    asm volatile("cp.async.wait_group %0;" :: "n"(N) : "memory");
}

static __device__ __forceinline__ float sigf(float x) {
    return __fdividef(1.f, 1.f + __expf(-x));
}
static __device__ __forceinline__ float tanf_fast(float x) {
    return __fdividef(2.f, 1.f + __expf(-2.f * x)) - 1.f;
}

static __device__ __forceinline__ void barp(int p) {
    asm volatile("bar.sync %0, 64;" :: "r"(p + 1) : "memory");
}

static __device__ __forceinline__ void grid_barrier(int d) {
    __threadfence();
    __syncthreads();
    if (threadIdx.x == 0) {
        ull* ctr = &g_barc[d * 16];
        ull old;
        asm volatile("atom.release.gpu.global.add.u64 %0, [%1], 1;"
                     : "=l"(old) : "l"(ctr) : "memory");
        ull target = (old / 64ULL + 1ULL) * 64ULL;
        ull cur = old + 1ULL;
        while (cur < target) {
            asm volatile("ld.acquire.gpu.global.u64 %0, [%1];"
                         : "=l"(cur) : "l"(ctr) : "memory");
            if (cur < target) __nanosleep(20);
        }
        __threadfence();
    }
    __syncthreads();
}

// phase-1 stage: 32k x 64b chunk, b-major rows (stride sstr), no commit
static __device__ __forceinline__ void stage32(unsigned dst, const float* sb,
                                               int sstr, int t2) {
#pragma unroll
    for (int j = 0; j < 8; ++j) {
        int idx = t2 + j * 64;
        int b = idx >> 3, f = idx & 7;
        cpa16(dst + (unsigned)(b * VROWB + f * 16),
              (const float4*)(sb + (size_t)b * sstr) + f);
    }
}
// phase-2 stage: contiguous 8KB copy, no commit
static __device__ __forceinline__ void stage32C(unsigned dst, const float* sb, int t2) {
#pragma unroll
    for (int j = 0; j < 8; ++j) {
        int idx = t2 + j * 64;
        cpa16(dst + (unsigned)idx * 16u, (const float4*)sb + idx);
    }
}

// shared fma body (48 fma.f32x2)
#define FMABODY \
  R0=fma2(a0,qa0,R0); R0=fma2(a1,qa1,R0); \
  R1=fma2(e0,qa0,R1); R1=fma2(e1,qa1,R1); \
  R2=fma2(f0,qa0,R2); R2=fma2(f1,qa1,R2); \
  R3=fma2(g0,qa0,R3); R3=fma2(g1,qa1,R3); \
  R4=fma2(a0,qb0,R4); R4=fma2(a1,qb1,R4); \
  R5=fma2(e0,qb0,R5); R5=fma2(e1,qb1,R5); \
  R6=fma2(f0,qb0,R6); R6=fma2(f1,qb1,R6); \
  R7=fma2(g0,qb0,R7); R7=fma2(g1,qb1,R7); \
  Z0=fma2(a0,sa0,Z0); Z0=fma2(a1,sa1,Z0); \
  Z1=fma2(e0,sa0,Z1); Z1=fma2(e1,sa1,Z1); \
  Z2=fma2(f0,sa0,Z2); Z2=fma2(f1,sa1,Z2); \
  Z3=fma2(g0,sa0,Z3); Z3=fma2(g1,sa1,Z3); \
  Z4=fma2(a0,sb0,Z4); Z4=fma2(a1,sb1,Z4); \
  Z5=fma2(e0,sb0,Z5); Z5=fma2(e1,sb1,Z5); \
  Z6=fma2(f0,sb0,Z6); Z6=fma2(f1,sb1,Z6); \
  Z7=fma2(g0,sb0,Z7); Z7=fma2(g1,sb1,Z7); \
  N0=fma2(a0,wa0,N0); N0=fma2(a1,wa1,N0); \
  N1=fma2(e0,wa0,N1); N1=fma2(e1,wa1,N1); \
  N2=fma2(f0,wa0,N2); N2=fma2(f1,wa1,N2); \
  N3=fma2(g0,wa0,N3); N3=fma2(g1,wa1,N3); \
  N4=fma2(a0,wb0,N4); N4=fma2(a1,wb1,N4); \
  N5=fma2(e0,wb0,N5); N5=fma2(e1,wb1,N5); \
  N6=fma2(f0,wb0,N6); N6=fma2(f1,wb1,N6); \
  N7=fma2(g0,wb0,N7); N7=fma2(g1,wb1,N7);

// phase-1 GITER (old b-major v layout): 10 LDS.128
#define GITER(O) { \
  ull a0,a1,e0,e1,f0,f1,g0,g1; \
  ull qa0,qa1,qb0,qb1, sa0,sa1,sb0,sb1, wa0,wa1,wb0,wb1; \
  LDS128O(va0,O,a0,a1); LDS128O(va1,O,e0,e1); \
  LDS128O(va2,O,f0,f1); LDS128O(va3,O,g0,g1); \
  LDS128O(xr0,O,qa0,qa1); LDS128O(xr1,O,qb0,qb1); \
  LDS128O(xz0,O,sa0,sa1); LDS128O(xz1,O,sb0,sb1); \
  LDS128O(xn0,O,wa0,wa1); LDS128O(xn1,O,wb0,wb1); \
  FMABODY }

#define COMPUTE_CHUNK(SLOT, KK) { \
  const unsigned va0 = (SLOT) + vb0, va1 = (SLOT) + vb1, \
                 va2 = (SLOT) + vb2, va3 = (SLOT) + vb3; \
  const unsigned xr0 = wr0 + (unsigned)(KK)*4u, xr1 = wr1 + (unsigned)(KK)*4u; \
  const unsigned xz0 = wz0 + (unsigned)(KK)*4u, xz1 = wz1 + (unsigned)(KK)*4u; \
  const unsigned xn0 = wn0 + (unsigned)(KK)*4u, xn1 = wn1 + (unsigned)(KK)*4u; \
  GITER(0)  GITER(16) GITER(32) GITER(48) \
  GITER(64) GITER(80) GITER(96) GITER(112) }

// phase-2 GITER (kp-major v layout): 8 LDS.64 (1 wf each) + 6 LDS.128 (broadcast)
#define GITER2(OV0, OV1, OW) { \
  ull a0,a1,e0,e1,f0,f1,g0,g1; \
  ull qa0,qa1,qb0,qb1, sa0,sa1,sb0,sb1, wa0,wa1,wb0,wb1; \
  LDS64O(ua0,OV0,a0); LDS64O(ua0,OV1,a1); \
  LDS64O(ua1,OV0,e0); LDS64O(ua1,OV1,e1); \
  LDS64O(ua2,OV0,f0); LDS64O(ua2,OV1,f1); \
  LDS64O(ua3,OV0,g0); LDS64O(ua3,OV1,g1); \
  LDS128O(xr0,OW,qa0,qa1); LDS128O(xr1,OW,qb0,qb1); \
  LDS128O(xz0,OW,sa0,sa1); LDS128O(xz1,OW,sb0,sb1); \
  LDS128O(xn0,OW,wa0,wa1); LDS128O(xn1,OW,wb0,wb1); \
  FMABODY }

#define COMPUTE_CHUNK2(SLOT, KK) { \
  const unsigned ua0 = (SLOT) + (unsigned)(bb*8), ua1 = ua0 + 128u, \
                 ua2 = ua0 + 256u, ua3 = ua0 + 384u; \
  const unsigned xr0 = wr0 + (unsigned)(KK)*4u, xr1 = wr1 + (unsigned)(KK)*4u; \
  const unsigned xz0 = wz0 + (unsigned)(KK)*4u, xz1 = wz1 + (unsigned)(KK)*4u; \
  const unsigned xn0 = wn0 + (unsigned)(KK)*4u, xn1 = wn1 + (unsigned)(KK)*4u; \
  GITER2(0,512,0)       GITER2(1024,1536,16) \
  GITER2(2048,2560,32)  GITER2(3072,3584,48) \
  GITER2(4096,4608,64)  GITER2(5120,5632,80) \
  GITER2(6144,6656,96)  GITER2(7168,7680,112) }

#define P1ST(ACC, GA, CG, G, BI) \
  xgrow[((GA)*8 + cg4 + 4*(CG))*64 + bb + 16*(G)] = lof(ACC) + hif(ACC) + (BI);

#define PUB(GA, M, ACC) rp[(GA)*512 + (M)*64 + t2] = lof(ACC) + hif(ACC);

// ---------------- persistent fused BiGRU ----------------
extern "C" __global__ void __launch_bounds__(NTHR, 1)
gru_persist(const float* __restrict__ data,
            const float* __restrict__ Wi_f, const float* __restrict__ bi_f,
            const float* __restrict__ Wh_f, const float* __restrict__ bhn_f,
            const float* __restrict__ Wi_b, const float* __restrict__ bi_b,
            const float* __restrict__ Wh_b, const float* __restrict__ bhn_b,
            float* __restrict__ out) {
    extern __shared__ float smem[];
    float* Ws   = smem;                                  // [24][772]
    float* redF = (float*)((char*)smem + WS_BYTES);      // overlays phase-2 slots

    const int tid = threadIdx.x;
    const int bid = blockIdx.x;
    const int d   = bid >> 6;
    const int cb  = (bid & 63) * 8;

    const float* Wi  = d ? Wi_b  : Wi_f;
    const float* Wh  = d ? Wh_b  : Wh_f;
    const float* bi  = d ? bi_b  : bi_f;
    const float* bhn = d ? bhn_b : bhn_f;

    for (int idx = tid; idx < 24 * 768; idx += NTHR) {
        int k = idx / 24, j = idx - k * 24;
        int g = j >> 3, cc = j & 7;
        int gcol = g * Hh + cb + cc;
        Ws[j * WSTRIDE + k] = (k < Ff) ? Wi[(size_t)k * (3 * Hh) + gcol]
                                       : Wh[(size_t)(k - Ff) * (3 * Hh) + gcol];
    }
    // zero my 8 h-columns of slot 0: contiguous 512 floats in kp layout
    ((float*)&g_h[d][0][cb >> 1][0][0])[tid] = 0.f;

    const int p   = tid >> 6;
    const int t2  = tid & 63;
    const int bb  = t2 & 15;
    const int cg4 = t2 >> 4;

    // epilogue cell mapping (cell m = tid)
    const int eM  = tid >> 6, et2 = tid & 63;
    const int ebq = (et2 & 15) + 16 * (eM & 3);
    const int ecc = (et2 >> 4) + 4 * (eM >> 2);
    const float ebh = bhn[cb + ecc];

    const float bi00 = bi[cb + cg4],        bi01 = bi[cb + cg4 + 4];
    const float bi10 = bi[Hh + cb + cg4],   bi11 = bi[Hh + cb + cg4 + 4];
    const float bi20 = bi[2*Hh + cb + cg4], bi21 = bi[2*Hh + cb + cg4 + 4];

    const unsigned wsA = (unsigned)__cvta_generic_to_shared(Ws);
    const unsigned vsA = (unsigned)__cvta_generic_to_shared((char*)smem + WS_BYTES);
    const unsigned xgA = vsA + 131072u;    // after 16 phase-2 slots
    const unsigned vb0 = (unsigned)(bb        * VROWB);
    const unsigned vb1 = (unsigned)((bb + 16) * VROWB);
    const unsigned vb2 = (unsigned)((bb + 32) * VROWB);
    const unsigned vb3 = (unsigned)((bb + 48) * VROWB);
    const unsigned wr0 = wsA + (unsigned)((0  + cg4)     * WSTRIDE) * 4u;
    const unsigned wr1 = wsA + (unsigned)((0  + cg4 + 4) * WSTRIDE) * 4u;
    const unsigned wz0 = wsA + (unsigned)((8  + cg4)     * WSTRIDE) * 4u;
    const unsigned wz1 = wsA + (unsigned)((8  + cg4 + 4) * WSTRIDE) * 4u;
    const unsigned wn0 = wsA + (unsigned)((16 + cg4)     * WSTRIDE) * 4u;
    const unsigned wn1 = wsA + (unsigned)((16 + cg4 + 4) * WSTRIDE) * 4u;

    // ===== PHASE 1: xg = x@Wi + bi (old layout slots; partition p owns t = 8j+p) =====
    {
        const unsigned SA = vsA + (unsigned)(2 * p)     * VSLOTB;
        const unsigned SB = vsA + (unsigned)(2 * p + 1) * VSLOTB;
        stage32(SA, data + (size_t)p * Ff,      TFs, t2); cpa_commit();
        stage32(SB, data + (size_t)p * Ff + 32, TFs, t2); cpa_commit();

        for (int jt = 0; jt < 64; ++jt) {
            const int t = 8 * jt + p;
            ull R0=0,R1=0,R2=0,R3=0,R4=0,R5=0,R6=0,R7=0;
            ull Z0=0,Z1=0,Z2=0,Z3=0,Z4=0,Z5=0,Z6=0,Z7=0;
            ull N0=0,N1=0,N2=0,N3=0,N4=0,N5=0,N6=0,N7=0;

            #pragma unroll 1
            for (int j = 0; j < 8; ++j) {
                if (jt == 63 && j == 7) { cpa_wait<0>(); } else { cpa_wait<1>(); }
                barp(p);
                COMPUTE_CHUNK((j & 1) ? SB : SA, 32 * j);
                barp(p);
                if (jt < 63 || j < 6) {
                    const int tS = (j < 6) ? t : t + 8;
                    const int kS = ((j + 2) & 7) * 32;
                    stage32((j & 1) ? SB : SA, data + (size_t)tS * Ff + kS, TFs, t2);
                    cpa_commit();
                }
            }

            float* xgrow = &g_xg[bid][t][0];
            P1ST(R0,0,0,0,bi00) P1ST(R1,0,0,1,bi00) P1ST(R2,0,0,2,bi00) P1ST(R3,0,0,3,bi00)
            P1ST(R4,0,1,0,bi01) P1ST(R5,0,1,1,bi01) P1ST(R6,0,1,2,bi01) P1ST(R7,0,1,3,bi01)
            P1ST(Z0,1,0,0,bi10) P1ST(Z1,1,0,1,bi10) P1ST(Z2,1,0,2,bi10) P1ST(Z3,1,0,3,bi10)
            P1ST(Z4,1,1,0,bi11) P1ST(Z5,1,1,1,bi11) P1ST(Z6,1,1,2,bi11) P1ST(Z7,1,1,3,bi11)
            P1ST(N0,2,0,0,bi20) P1ST(N1,2,0,1,bi20) P1ST(N2,2,0,2,bi20) P1ST(N3,2,0,3,bi20)
            P1ST(N4,2,1,0,bi21) P1ST(N5,2,1,1,bi21) P1ST(N6,2,1,2,bi21) P1ST(N7,2,1,3,bi21)
        }
    }

    grid_barrier(d);   // xg + h zeros + weights visible chip-wide

    // ===== PHASE 2: recurrence (kp-layout slots: partition p has 16KB at p*16384) =====
    const unsigned SA2 = vsA + (unsigned)p * 16384u;
    const unsigned SB2 = SA2 + (unsigned)VSLOTB2;
    const int K0h = p * 64;

    {
        const float* hb = &g_h[d][0][0][0][0];
        stage32C(SA2, hb + K0h * 64, t2);
        if (p == 0) {
            const float4* xs = (const float4*)&g_xg[bid][0][0];
            #pragma unroll
            for (int i = 0; i < 6; ++i)
                cpa16(xgA + (unsigned)((t2 + i * 64) * 16), xs + t2 + i * 64);
        }
        cpa_commit();
        stage32C(SB2, hb + K0h * 64 + 2048, t2);
        cpa_commit();
    }

    for (int t = 0; t < Tt; ++t) {
        const int rs = t & 1;
        const int ws = rs ^ 1;

        ull R0=0,R1=0,R2=0,R3=0,R4=0,R5=0,R6=0,R7=0;
        ull Z0=0,Z1=0,Z2=0,Z3=0,Z4=0,Z5=0,Z6=0,Z7=0;
        ull N0=0,N1=0,N2=0,N3=0,N4=0,N5=0,N6=0,N7=0;

        cpa_wait<1>(); barp(p);
        COMPUTE_CHUNK2(SA2, 256 + K0h);
        cpa_wait<0>(); barp(p);
        COMPUTE_CHUNK2(SB2, 256 + K0h + 32);
        barp(p);   // partition done reading its slots (+compiler fence)

        {   // publish f32 partials into OWN slot region (16KB stride)
            float* rp = redF + (size_t)p * 4096;
            PUB(0,0,R0) PUB(0,1,R1) PUB(0,2,R2) PUB(0,3,R3)
            PUB(0,4,R4) PUB(0,5,R5) PUB(0,6,R6) PUB(0,7,R7)
            PUB(1,0,Z0) PUB(1,1,Z1) PUB(1,2,Z2) PUB(1,3,Z3)
            PUB(1,4,Z4) PUB(1,5,Z5) PUB(1,6,Z6) PUB(1,7,Z7)
            PUB(2,0,N0) PUB(2,1,N1) PUB(2,2,N2) PUB(2,3,N3)
            PUB(2,4,N4) PUB(2,5,N5) PUB(2,6,N6) PUB(2,7,N7)
        }
        __syncthreads();

        {   // distributed epilogue: thread finalizes cell m = tid
            float Rm = 0.f, Zm = 0.f, Nm = 0.f;
            #pragma unroll
            for (int q = 0; q < 8; ++q) {
                const float* e = redF + (size_t)q * 4096;
                Rm += e[tid]; Zm += e[512 + tid]; Nm += e[1024 + tid];
            }
            const float* xgS = (const float*)((char*)smem + WS_BYTES + 131072);
            float xr = xgS[(0*8 + ecc) * 64 + ebq];
            float xz = xgS[(1*8 + ecc) * 64 + ebq];
            float xn = xgS[(2*8 + ecc) * 64 + ebq];
            float hprev = g_h[d][rs][(cb + ecc) >> 1][ebq][ecc & 1];
            float rv = sigf(xr + Rm);
            float zv = sigf(xz + Zm);
            float nv = tanf_fast(xn + rv * (Nm + ebh));
            float hnew = (1.f - zv) * nv + zv * hprev;
            g_h[d][ws][(cb + ecc) >> 1][ebq][ecc & 1] = hnew;
            out[(size_t)ebq * OST + (size_t)t * (2 * Hh) + (size_t)d * Hh + cb + ecc] = hnew;
        }

        grid_barrier(d);

        if (t + 1 < Tt) {
            const float* hb = &g_h[d][ws][0][0][0];
            stage32C(SA2, hb + K0h * 64, t2);
            if (p == 0) {
                const float4* xs = (const float4*)&g_xg[bid][t + 1][0];
                #pragma unroll
                for (int i = 0; i < 6; ++i)
                    cpa16(xgA + (unsigned)((t2 + i * 64) * 16), xs + t2 + i * 64);
            }
            cpa_commit();
            stage32C(SB2, hb + K0h * 64 + 2048, t2);
            cpa_commit();
        }
    }
}

extern "C" void kernel_launch(void* const* d_in, const int* in_sizes, int n_in,
                              void* d_out, int out_size) {
    const float* data  = (const float*)d_in[0];
    const float* Wi_f  = (const float*)d_in[1];
    const float* bi_f  = (const float*)d_in[2];
    const float* Wh_f  = (const float*)d_in[3];
    const float* bhn_f = (const float*)d_in[4];
    const float* Wi_b  = (const float*)d_in[5];
    const float* bi_b  = (const float*)d_in[6];
    const float* Wh_b  = (const float*)d_in[7];
    const float* bhn_b = (const float*)d_in[8];
    float* out = (float*)d_out;

    cudaFuncSetAttribute(gru_persist, cudaFuncAttributeMaxDynamicSharedMemorySize, SMEM_BYTES);

    gru_persist<<<GRIDN, NTHR, SMEM_BYTES>>>(data, Wi_f, bi_f, Wh_f, bhn_f,
                                             Wi_b, bi_b, Wh_b, bhn_b, out);
}